// round 9
// baseline (speedup 1.0000x reference)
#include <cuda_runtime.h>
#include <cstdint>

#define NROWS 65536
#define DDIM 512
#define NUM_LABELS 512
#define NUM_DEMOG 4
#define NGROUP (NUM_LABELS * NUM_DEMOG)

#define GRID_STREAM 444          /* 148 SMs x 3 CTAs: one wave guaranteed */
#define TS 128                   /* threads per stream CTA (R5-measured best) */
#define CHUNK 148                /* rows per CTA (444*148 = 65712 >= 65536) */
#define BR 8                     /* rows per batch */
#define NB 4                     /* ring depth in batches */
#define CHUNK_PAD 152            /* ceil(148/8)*8 */
#define NBATCH 19                /* CHUNK_PAD / BR */
#define ROWB 2048                /* bytes per row */

// ---- persistent device state (statically zero at load; self-cleaning) ----
__device__ int    g_cnt[NGROUP];          // zeroed by pass2 after read
__device__ int    g_off[NGROUP + 1];      // overwritten each run
__device__ int    g_cursor[NGROUP];       // overwritten each run
__device__ int    g_sorted[NROWS];        // overwritten each run
__device__ int    g_seg_sorted[NROWS];    // overwritten each run
__device__ float4 g_sums4[NGROUP * (DDIM / 4)];  // zeroed by pass2 after read
__device__ float  g_ssq[NGROUP];          // zeroed by pass2 after read
__device__ double g_gm[NGROUP];           // overwritten each run
__device__ int    g_hist_done;            // reset by finalize
__device__ volatile int g_prep_flag;      // reset by finalize
__device__ int    g_stream_done;          // reset by finalize
__device__ int    g_fin_done;             // reset by finalize

__device__ __forceinline__ int load_idx_val(const void* p, int i, int is64) {
    if (is64) return (int)((const long long*)p)[i];
    return ((const int*)p)[i];
}

// ===== k_prep: hist -> last-CTA scan -> flag sync -> scatter =====
// 64 CTAs x 1024 threads: <=1 CTA/SM, single wave => spin safe.
__global__ void __launch_bounds__(1024) k_prep(const void* labels, const void* demog) {
    int i = blockIdx.x * 1024 + threadIdx.x;      // 64 x 1024 = 65536 exactly
    int t = threadIdx.x;

    // dtype detect per CTA (cheap; avoids extra kernel)
    __shared__ int s_is64;
    if (t == 0) {
        const int* lr = (const int*)labels;
        int nz = 0;
        for (int k = 1; k < 64; k += 2) nz += (lr[k] != 0);
        s_is64 = (nz == 0) ? 1 : 0;
    }
    __syncthreads();
    int is64 = s_is64;

    int lab = load_idx_val(labels, i, is64);
    int dem = load_idx_val(demog, i, is64);
    int seg = dem * NUM_LABELS + lab;
    atomicAdd(&g_cnt[seg], 1);

    __shared__ int s_last;
    __threadfence();
    __syncthreads();
    if (t == 0)
        s_last = (atomicAdd(&g_hist_done, 1) == gridDim.x - 1) ? 1 : 0;
    __syncthreads();

    if (s_last) {
        __threadfence();   // acquire: all g_cnt visible
        int lane = t & 31, warp = t >> 5;
        int a = g_cnt[2 * t];
        int b = g_cnt[2 * t + 1];
        int pair = a + b;
        int v = pair;
        #pragma unroll
        for (int d = 1; d < 32; d <<= 1) {
            int u = __shfl_up_sync(0xffffffffu, v, d);
            if (lane >= d) v += u;
        }
        __shared__ int wsum[32];
        if (lane == 31) wsum[warp] = v;
        __syncthreads();
        if (warp == 0) {
            int w = wsum[lane];
            int x = w;
            #pragma unroll
            for (int d = 1; d < 32; d <<= 1) {
                int u = __shfl_up_sync(0xffffffffu, x, d);
                if (lane >= d) x += u;
            }
            wsum[lane] = x - w;
        }
        __syncthreads();
        int incl = v + wsum[warp];
        int excl = incl - pair;
        g_off[2 * t]        = excl;
        g_off[2 * t + 1]    = excl + a;
        g_cursor[2 * t]     = excl;
        g_cursor[2 * t + 1] = excl + a;
        if (t == 1023) g_off[2048] = incl;
        __threadfence();
        __syncthreads();
        if (t == 0) g_prep_flag = 1;
    } else {
        if (t == 0) { while (g_prep_flag == 0) { __nanosleep(32); } }
        __syncthreads();
        __threadfence();   // acquire: g_cursor visible
    }

    int pos = atomicAdd(&g_cursor[seg], 1);
    g_sorted[pos] = i;
    g_seg_sorted[pos] = seg;
}

// ---------------- cp.async helpers ----------------
__device__ __forceinline__ void cp_async16(uint32_t dst, const float* src) {
    asm volatile("cp.async.cg.shared.global [%0], [%1], 16;" :: "r"(dst), "l"(src));
}
__device__ __forceinline__ void cp_commit() { asm volatile("cp.async.commit_group;" ::: "memory"); }
__device__ __forceinline__ void cp_wait0() { asm volatile("cp.async.wait_group 0;" ::: "memory"); }
__device__ __forceinline__ void cp_wait1() { asm volatile("cp.async.wait_group 1;" ::: "memory"); }
__device__ __forceinline__ void cp_wait2() { asm volatile("cp.async.wait_group 2;" ::: "memory"); }

// ===== k_stream: R5-measured streaming body + grid sync + pass2 + finalize =====
extern "C" __global__ void __launch_bounds__(TS, 3) k_stream(const float* __restrict__ feats,
                                                             float* __restrict__ out) {
    extern __shared__ __align__(16) char sm[];
    float* ring = (float*)sm;                                  // NB*BR*ROWB = 64 KB
    int*   sidx = (int*)(sm + NB * BR * ROWB);                 // CHUNK_PAD ints
    int*   sseg = sidx + CHUNK_PAD;                            // CHUNK_PAD ints

    int bid = blockIdx.x, t = threadIdx.x;
    int lo = bid * CHUNK;
    int lane = t & 31;

    for (int i = t; i < CHUNK_PAD; i += TS) {
        int gi = lo + i;
        if (i < CHUNK && gi < NROWS) {
            sidx[i] = g_sorted[gi];
            sseg[i] = g_seg_sorted[gi];
        } else {
            sidx[i] = 0;
            sseg[i] = -1;        // pad: loaded but never accumulated
        }
    }
    __syncthreads();

    uint32_t ring_base = (uint32_t)__cvta_generic_to_shared(ring) + (uint32_t)t * 16u;
    const float* fbase = feats + (t << 2);

    // prologue: issue batches 0..2
    #pragma unroll
    for (int p = 0; p < 3; ++p) {
        #pragma unroll
        for (int r = 0; r < BR; ++r) {
            const float* src = fbase + ((size_t)sidx[p * BR + r] << 9);
            cp_async16(ring_base + (uint32_t)((p & (NB - 1)) * BR + r) * ROWB, src);
        }
        cp_commit();
    }

    float4 acc = make_float4(0.f, 0.f, 0.f, 0.f);
    float  ssq = 0.f;
    int    cur = -1;

    for (int b = 0; b < NBATCH; ++b) {
        int k = NBATCH - 1 - b;
        if (k >= 2) cp_wait2(); else if (k == 1) cp_wait1(); else cp_wait0();

        const float* bp = ring + (size_t)((b & (NB - 1)) * BR) * DDIM + (t << 2);
        #pragma unroll
        for (int r = 0; r < BR; ++r) {
            int sg = sseg[b * BR + r];
            if (sg != cur) {
                if (cur >= 0) {
                    float* dst = (float*)g_sums4 + ((size_t)cur << 9) + (t << 2);
                    atomicAdd(dst + 0, acc.x);
                    atomicAdd(dst + 1, acc.y);
                    atomicAdd(dst + 2, acc.z);
                    atomicAdd(dst + 3, acc.w);
                    float ws = ssq;
                    #pragma unroll
                    for (int o = 16; o > 0; o >>= 1)
                        ws += __shfl_down_sync(0xffffffffu, ws, o);
                    if (lane == 0) atomicAdd(&g_ssq[cur], ws);
                }
                acc = make_float4(0.f, 0.f, 0.f, 0.f);
                ssq = 0.f;
                cur = sg;
            }
            if (sg >= 0) {
                float4 v = *(const float4*)(bp + (size_t)r * DDIM);
                acc.x += v.x; acc.y += v.y; acc.z += v.z; acc.w += v.w;
                ssq += v.x * v.x + v.y * v.y + v.z * v.z + v.w * v.w;
            }
        }
        int nxt = b + 3;
        if (nxt < NBATCH) {
            #pragma unroll
            for (int r = 0; r < BR; ++r) {
                const float* src = fbase + ((size_t)sidx[nxt * BR + r] << 9);
                cp_async16(ring_base + (uint32_t)((nxt & (NB - 1)) * BR + r) * ROWB, src);
            }
            cp_commit();
        }
    }
    if (cur >= 0) {
        float* dst = (float*)g_sums4 + ((size_t)cur << 9) + (t << 2);
        atomicAdd(dst + 0, acc.x);
        atomicAdd(dst + 1, acc.y);
        atomicAdd(dst + 2, acc.z);
        atomicAdd(dst + 3, acc.w);
        float ws = ssq;
        #pragma unroll
        for (int o = 16; o > 0; o >>= 1)
            ws += __shfl_down_sync(0xffffffffu, ws, o);
        if (lane == 0) atomicAdd(&g_ssq[cur], ws);
    }

    // ---- grid sync (all 444 CTAs resident: 3/SM at 66.9 KB <= 228 KB) ----
    __threadfence();
    __syncthreads();
    if (t == 0) {
        int v = atomicAdd(&g_stream_done, 1) + 1;
        if (v < GRID_STREAM)
            while (*(volatile int*)&g_stream_done < GRID_STREAM) __nanosleep(64);
    }
    __syncthreads();
    __threadfence();   // acquire

    // ---- fused pass2: one warp per group; self-clean after read ----
    int w = t >> 5;   // 4 warps
    for (int gidx = w * GRID_STREAM + bid; gidx < NGROUP; gidx += 4 * GRID_STREAM) {
        double nn = 0.0;
        #pragma unroll
        for (int j = 0; j < 4; ++j) {
            float4 v = g_sums4[(size_t)gidx * 128 + lane + 32 * j];
            nn += (double)v.x * v.x + (double)v.y * v.y +
                  (double)v.z * v.z + (double)v.w * v.w;
        }
        float4 z = make_float4(0.f, 0.f, 0.f, 0.f);
        #pragma unroll
        for (int j = 0; j < 4; ++j)
            g_sums4[(size_t)gidx * 128 + lane + 32 * j] = z;
        #pragma unroll
        for (int o = 16; o > 0; o >>= 1)
            nn += __shfl_down_sync(0xffffffffu, nn, o);
        if (lane == 0) {
            int cnt = g_cnt[gidx];
            double den = (cnt > 0) ? (double)cnt : 1.0;
            g_gm[gidx] = ((double)g_ssq[gidx] - nn / den) / den;
            g_ssq[gidx] = 0.f;
            g_cnt[gidx] = 0;
        }
    }

    // ---- last-CTA finalize (scratch aliased onto dead ring) ----
    __shared__ int s_last;
    __threadfence();
    __syncthreads();
    if (t == 0)
        s_last = (atomicAdd(&g_fin_done, 1) == GRID_STREAM - 1) ? 1 : 0;
    __syncthreads();
    if (!s_last) return;
    __threadfence();

    double* fsum = (double*)sm;                                   // 4*128 doubles = 4 KB
    int*    fcnt = (int*)(sm + NUM_DEMOG * TS * sizeof(double));  // 2 KB

    double lsum[NUM_DEMOG] = {0.0, 0.0, 0.0, 0.0};
    int    lcnt[NUM_DEMOG] = {0, 0, 0, 0};
    for (int gg = t; gg < NGROUP; gg += TS) {
        if (g_off[gg + 1] - g_off[gg] > 0) {    // presence from offsets
            int d = gg >> 9;
            lsum[d] += g_gm[gg];
            lcnt[d] += 1;
        }
    }
    #pragma unroll
    for (int d = 0; d < NUM_DEMOG; ++d) {
        fsum[d * TS + t] = lsum[d];
        fcnt[d * TS + t] = lcnt[d];
    }
    __syncthreads();
    #pragma unroll
    for (int s = TS / 2; s > 0; s >>= 1) {
        if (t < s) {
            #pragma unroll
            for (int d = 0; d < NUM_DEMOG; ++d) {
                fsum[d * TS + t] += fsum[d * TS + t + s];
                fcnt[d * TS + t] += fcnt[d * TS + t + s];
            }
        }
        __syncthreads();
    }
    if (t == 0) {
        double intra[NUM_DEMOG];
        double mu = 0.0;
        #pragma unroll
        for (int d = 0; d < NUM_DEMOG; ++d) {
            int np = fcnt[d * TS] > 0 ? fcnt[d * TS] : 1;
            intra[d] = fsum[d * TS] / (double)np;
            mu += intra[d];
        }
        mu /= (double)NUM_DEMOG;
        double loss = 0.0;
        #pragma unroll
        for (int d = 0; d < NUM_DEMOG; ++d) loss += fabs(intra[d] - mu);
        loss /= (double)NUM_DEMOG;
        out[0] = (float)loss;

        // reset flags for the next graph replay
        g_hist_done = 0;
        g_prep_flag = 0;
        g_stream_done = 0;
        g_fin_done = 0;
        __threadfence();
    }
}

extern "C" void kernel_launch(void* const* d_in, const int* in_sizes, int n_in,
                              void* d_out, int out_size) {
    const float* feats  = (const float*)d_in[0];
    const void*  labels = d_in[1];
    const void*  demog  = d_in[2];
    float* out = (float*)d_out;

    const int smem_stream = NB * BR * ROWB + 2 * CHUNK_PAD * (int)sizeof(int) + 128;
    cudaFuncSetAttribute(k_stream, cudaFuncAttributeMaxDynamicSharedMemorySize, smem_stream);

    k_prep<<<64, 1024>>>(labels, demog);
    k_stream<<<GRID_STREAM, TS, smem_stream>>>(feats, out);
}

// round 10
// speedup vs baseline: 1.1073x; 1.1073x over previous
#include <cuda_runtime.h>
#include <cstdint>

#define NROWS 65536
#define DDIM 512
#define NUM_LABELS 512
#define NUM_DEMOG 4
#define NGROUP (NUM_LABELS * NUM_DEMOG)

#define GRID_STREAM 444          /* 148 SMs x 3 CTAs: one wave */
#define TS 128                   /* threads per stream CTA (R5-measured best) */
#define CHUNK 148                /* rows per CTA (444*148 = 65712 >= 65536) */
#define BR 8                     /* rows per batch */
#define NB 4                     /* ring depth in batches */
#define CHUNK_PAD 152            /* ceil(148/8)*8 */
#define NBATCH 19                /* CHUNK_PAD / BR */
#define ROWB 2048                /* bytes per row */

#define HIST_BLOCKS 64
#define ZERO_BLOCKS 32           /* zero 4MB g_sums4: 32*1024 thr * 8 float4 */
#define PREP_GRID (HIST_BLOCKS + ZERO_BLOCKS)

// ---- persistent device state (BSS zero at load; tiny parts self-cleaned) ----
__device__ int    g_cnt[NGROUP];          // zeroed by pass2 after read
__device__ int    g_off[NGROUP + 1];      // overwritten each run
__device__ int    g_cursor[NGROUP];       // overwritten each run
__device__ int    g_sorted[NROWS];        // overwritten each run
__device__ int    g_seg_sorted[NROWS];    // overwritten each run
__device__ float4 g_sums4[NGROUP * (DDIM / 4)];  // zeroed by k_prep zero-blocks (L2-warm!)
__device__ float  g_ssq[NGROUP];          // zeroed by k_prep zero-blocks
__device__ double g_gm[NGROUP];           // overwritten each run
__device__ int    g_hist_done;            // reset by pass2 finalize
__device__ volatile int g_prep_flag;      // reset by pass2 finalize
__device__ int    g_fin_done;             // reset by pass2 finalize

__device__ __forceinline__ int load_idx_val(const void* p, int i, int is64) {
    if (is64) return (int)((const long long*)p)[i];
    return ((const int*)p)[i];
}

// ===== k_prep: [blocks 0-63] hist -> scan -> scatter ; [blocks 64-95] zero sums =====
// 96 CTAs x 1024 threads: <= 1 CTA/SM, single wave => internal spin safe.
__global__ void __launch_bounds__(1024) k_prep(const void* labels, const void* demog) {
    int bid = blockIdx.x, t = threadIdx.x;

    if (bid >= HIST_BLOCKS) {
        // -------- zero blocks: warm g_sums4 (+g_ssq) into L2 as modified lines --------
        int zb = bid - HIST_BLOCKS;          // 0..31
        float4 z = make_float4(0.f, 0.f, 0.f, 0.f);
        size_t base = (size_t)zb * 1024 + t; // stride 32768 over 262144 float4s
        #pragma unroll
        for (int j = 0; j < 8; ++j)
            g_sums4[base + (size_t)j * 32768] = z;
        if (zb == 0) { g_ssq[t] = 0.f; g_ssq[t + 1024] = 0.f; }
        return;
    }

    int i = bid * 1024 + t;                  // 64 x 1024 = 65536 exactly

    __shared__ int s_is64;
    if (t == 0) {
        const int* lr = (const int*)labels;
        int nz = 0;
        for (int k = 1; k < 64; k += 2) nz += (lr[k] != 0);
        s_is64 = (nz == 0) ? 1 : 0;
    }
    __syncthreads();
    int is64 = s_is64;

    int lab = load_idx_val(labels, i, is64);
    int dem = load_idx_val(demog, i, is64);
    int seg = dem * NUM_LABELS + lab;
    atomicAdd(&g_cnt[seg], 1);

    __shared__ int s_last;
    __threadfence();
    __syncthreads();
    if (t == 0)
        s_last = (atomicAdd(&g_hist_done, 1) == HIST_BLOCKS - 1) ? 1 : 0;
    __syncthreads();

    if (s_last) {
        __threadfence();   // acquire: all g_cnt visible
        int lane = t & 31, warp = t >> 5;
        int a = g_cnt[2 * t];
        int b = g_cnt[2 * t + 1];
        int pair = a + b;
        int v = pair;
        #pragma unroll
        for (int d = 1; d < 32; d <<= 1) {
            int u = __shfl_up_sync(0xffffffffu, v, d);
            if (lane >= d) v += u;
        }
        __shared__ int wsum[32];
        if (lane == 31) wsum[warp] = v;
        __syncthreads();
        if (warp == 0) {
            int w = wsum[lane];
            int x = w;
            #pragma unroll
            for (int d = 1; d < 32; d <<= 1) {
                int u = __shfl_up_sync(0xffffffffu, x, d);
                if (lane >= d) x += u;
            }
            wsum[lane] = x - w;
        }
        __syncthreads();
        int incl = v + wsum[warp];
        int excl = incl - pair;
        g_off[2 * t]        = excl;
        g_off[2 * t + 1]    = excl + a;
        g_cursor[2 * t]     = excl;
        g_cursor[2 * t + 1] = excl + a;
        if (t == 1023) g_off[2048] = incl;
        __threadfence();
        __syncthreads();
        if (t == 0) g_prep_flag = 1;
    } else {
        if (t == 0) { while (g_prep_flag == 0) { __nanosleep(32); } }
        __syncthreads();
        __threadfence();   // acquire: g_cursor visible
    }

    int pos = atomicAdd(&g_cursor[seg], 1);
    g_sorted[pos] = i;
    g_seg_sorted[pos] = seg;
}

// ---------------- cp.async helpers ----------------
__device__ __forceinline__ void cp_async16(uint32_t dst, const float* src) {
    asm volatile("cp.async.cg.shared.global [%0], [%1], 16;" :: "r"(dst), "l"(src));
}
__device__ __forceinline__ void cp_commit() { asm volatile("cp.async.commit_group;" ::: "memory"); }
__device__ __forceinline__ void cp_wait0() { asm volatile("cp.async.wait_group 0;" ::: "memory"); }
__device__ __forceinline__ void cp_wait1() { asm volatile("cp.async.wait_group 1;" ::: "memory"); }
__device__ __forceinline__ void cp_wait2() { asm volatile("cp.async.wait_group 2;" ::: "memory"); }

// ===== k_stream: EXACT R5 body (measured 27.6us @ 5.2TB/s). Nothing appended. =====
extern "C" __global__ void __launch_bounds__(TS) k_stream(const float* __restrict__ feats) {
    extern __shared__ __align__(16) char sm[];
    float* ring = (float*)sm;                                  // NB*BR*ROWB = 64 KB
    int*   sidx = (int*)(sm + NB * BR * ROWB);                 // CHUNK_PAD ints
    int*   sseg = sidx + CHUNK_PAD;                            // CHUNK_PAD ints

    int bid = blockIdx.x, t = threadIdx.x;
    int lo = bid * CHUNK;

    for (int i = t; i < CHUNK_PAD; i += TS) {
        int gi = lo + i;
        if (i < CHUNK && gi < NROWS) {
            sidx[i] = g_sorted[gi];
            sseg[i] = g_seg_sorted[gi];
        } else {
            sidx[i] = 0;
            sseg[i] = -1;
        }
    }
    __syncthreads();

    uint32_t ring_base = (uint32_t)__cvta_generic_to_shared(ring) + (uint32_t)t * 16u;
    const float* fbase = feats + (t << 2);

    #pragma unroll
    for (int p = 0; p < 3; ++p) {
        #pragma unroll
        for (int r = 0; r < BR; ++r) {
            const float* src = fbase + ((size_t)sidx[p * BR + r] << 9);
            cp_async16(ring_base + (uint32_t)((p & (NB - 1)) * BR + r) * ROWB, src);
        }
        cp_commit();
    }

    float4 acc = make_float4(0.f, 0.f, 0.f, 0.f);
    float  ssq = 0.f;
    int    cur = -1;
    int    lane = t & 31;

    for (int b = 0; b < NBATCH; ++b) {
        int k = NBATCH - 1 - b;
        if (k >= 2) cp_wait2(); else if (k == 1) cp_wait1(); else cp_wait0();

        const float* bp = ring + (size_t)((b & (NB - 1)) * BR) * DDIM + (t << 2);
        #pragma unroll
        for (int r = 0; r < BR; ++r) {
            int sg = sseg[b * BR + r];
            if (sg != cur) {
                if (cur >= 0) {
                    float* dst = (float*)g_sums4 + ((size_t)cur << 9) + (t << 2);
                    atomicAdd(dst + 0, acc.x);
                    atomicAdd(dst + 1, acc.y);
                    atomicAdd(dst + 2, acc.z);
                    atomicAdd(dst + 3, acc.w);
                    float ws = ssq;
                    #pragma unroll
                    for (int o = 16; o > 0; o >>= 1)
                        ws += __shfl_down_sync(0xffffffffu, ws, o);
                    if (lane == 0) atomicAdd(&g_ssq[cur], ws);
                }
                acc = make_float4(0.f, 0.f, 0.f, 0.f);
                ssq = 0.f;
                cur = sg;
            }
            if (sg >= 0) {
                float4 v = *(const float4*)(bp + (size_t)r * DDIM);
                acc.x += v.x; acc.y += v.y; acc.z += v.z; acc.w += v.w;
                ssq += v.x * v.x + v.y * v.y + v.z * v.z + v.w * v.w;
            }
        }
        int nxt = b + 3;
        if (nxt < NBATCH) {
            #pragma unroll
            for (int r = 0; r < BR; ++r) {
                const float* src = fbase + ((size_t)sidx[nxt * BR + r] << 9);
                cp_async16(ring_base + (uint32_t)((nxt & (NB - 1)) * BR + r) * ROWB, src);
            }
            cp_commit();
        }
    }
    if (cur >= 0) {
        float* dst = (float*)g_sums4 + ((size_t)cur << 9) + (t << 2);
        atomicAdd(dst + 0, acc.x);
        atomicAdd(dst + 1, acc.y);
        atomicAdd(dst + 2, acc.z);
        atomicAdd(dst + 3, acc.w);
        float ws = ssq;
        #pragma unroll
        for (int o = 16; o > 0; o >>= 1)
            ws += __shfl_down_sync(0xffffffffu, ws, o);
        if (lane == 0) atomicAdd(&g_ssq[cur], ws);
    }
}

// ===== k_pass2: per-group gm; last CTA finalizes; self-clean tiny state =====
__global__ void __launch_bounds__(128) k_pass2(float* __restrict__ out) {
    __shared__ double wred[4];
    int g = blockIdx.x, t = threadIdx.x;
    int lane = t & 31, w = t >> 5;

    float4 v = g_sums4[g * 128 + t];
    double nn = (double)v.x * v.x + (double)v.y * v.y +
                (double)v.z * v.z + (double)v.w * v.w;
    #pragma unroll
    for (int o = 16; o > 0; o >>= 1)
        nn += __shfl_down_sync(0xffffffffu, nn, o);
    if (lane == 0) wred[w] = nn;
    __syncthreads();
    if (t == 0) {
        double normsq = wred[0] + wred[1] + wred[2] + wred[3];
        int cnt = g_cnt[g];
        double den = (cnt > 0) ? (double)cnt : 1.0;
        g_gm[g] = ((double)g_ssq[g] - normsq / den) / den;
        g_cnt[g] = 0;   // self-clean for next replay (presence via g_off later)
    }

    // ---- last-CTA finalize ----
    __shared__ int s_last;
    __threadfence();
    __syncthreads();
    if (t == 0)
        s_last = (atomicAdd(&g_fin_done, 1) == NGROUP - 1) ? 1 : 0;
    __syncthreads();
    if (!s_last) return;
    __threadfence();

    __shared__ double fsum[NUM_DEMOG][128];
    __shared__ int    fcnt[NUM_DEMOG][128];
    double lsum[NUM_DEMOG] = {0.0, 0.0, 0.0, 0.0};
    int    lcnt[NUM_DEMOG] = {0, 0, 0, 0};
    for (int gg = t; gg < NGROUP; gg += 128) {
        if (g_off[gg + 1] - g_off[gg] > 0) {
            int d = gg >> 9;
            lsum[d] += g_gm[gg];
            lcnt[d] += 1;
        }
    }
    #pragma unroll
    for (int d = 0; d < NUM_DEMOG; ++d) { fsum[d][t] = lsum[d]; fcnt[d][t] = lcnt[d]; }
    __syncthreads();
    #pragma unroll
    for (int s = 64; s > 0; s >>= 1) {
        if (t < s) {
            #pragma unroll
            for (int d = 0; d < NUM_DEMOG; ++d) {
                fsum[d][t] += fsum[d][t + s];
                fcnt[d][t] += fcnt[d][t + s];
            }
        }
        __syncthreads();
    }
    if (t == 0) {
        double intra[NUM_DEMOG];
        double mu = 0.0;
        #pragma unroll
        for (int d = 0; d < NUM_DEMOG; ++d) {
            int np = fcnt[d][0] > 0 ? fcnt[d][0] : 1;
            intra[d] = fsum[d][0] / (double)np;
            mu += intra[d];
        }
        mu /= (double)NUM_DEMOG;
        double loss = 0.0;
        #pragma unroll
        for (int d = 0; d < NUM_DEMOG; ++d) loss += fabs(intra[d] - mu);
        loss /= (double)NUM_DEMOG;
        out[0] = (float)loss;

        // reset flags for next graph replay
        g_hist_done = 0;
        g_prep_flag = 0;
        g_fin_done = 0;
        __threadfence();
    }
}

extern "C" void kernel_launch(void* const* d_in, const int* in_sizes, int n_in,
                              void* d_out, int out_size) {
    const float* feats  = (const float*)d_in[0];
    const void*  labels = d_in[1];
    const void*  demog  = d_in[2];
    float* out = (float*)d_out;

    const int smem_stream = NB * BR * ROWB + 2 * CHUNK_PAD * (int)sizeof(int) + 256;
    cudaFuncSetAttribute(k_stream, cudaFuncAttributeMaxDynamicSharedMemorySize, smem_stream);

    k_prep<<<PREP_GRID, 1024>>>(labels, demog);
    k_stream<<<GRID_STREAM, TS, smem_stream>>>(feats);
    k_pass2<<<NGROUP, 128>>>(out);
}

// round 11
// speedup vs baseline: 1.1179x; 1.0096x over previous
#include <cuda_runtime.h>
#include <cstdint>

#define NROWS 65536
#define DDIM 512
#define NUM_LABELS 512
#define NUM_DEMOG 4
#define NGROUP (NUM_LABELS * NUM_DEMOG)

#define GRID 444                 /* 148 SMs x 3 CTAs: exactly one wave */
#define TS 128                   /* proven stream block size */
#define CHUNK 148                /* rows per CTA (444*148 = 65712 >= 65536) */
#define BR 8
#define NB 4
#define CHUNK_PAD 152
#define NBATCH 19                /* CHUNK_PAD / BR */
#define ROWB 2048

// ---- persistent device state (BSS zero; self-cleaning each replay) ----
__device__ int    g_cnt[NGROUP];
__device__ int    g_off[NGROUP + 1];
__device__ int    g_cursor[NGROUP];
__device__ int    g_sorted[NROWS];
__device__ int    g_seg_sorted[NROWS];
__device__ float4 g_sums4[NGROUP * (DDIM / 4)];   // only boundary groups touched
__device__ float  g_ssq[NGROUP];
__device__ double g_intra[NUM_DEMOG];
__device__ int    g_present[NUM_DEMOG];
__device__ int    g_bar[4];
__device__ int    g_fin;

// ---------------- cp.async helpers ----------------
__device__ __forceinline__ void cp_async16(uint32_t dst, const float* src) {
    asm volatile("cp.async.cg.shared.global [%0], [%1], 16;" :: "r"(dst), "l"(src));
}
__device__ __forceinline__ void cp_commit() { asm volatile("cp.async.commit_group;" ::: "memory"); }
__device__ __forceinline__ void cp_wait0() { asm volatile("cp.async.wait_group 0;" ::: "memory"); }
__device__ __forceinline__ void cp_wait1() { asm volatile("cp.async.wait_group 1;" ::: "memory"); }
__device__ __forceinline__ void cp_wait2() { asm volatile("cp.async.wait_group 2;" ::: "memory"); }

// ---------------- grid barrier (all 444 CTAs resident, proven in R7) ----------------
__device__ __forceinline__ void grid_bar(int idx) {
    __syncthreads();
    if (threadIdx.x == 0) {
        __threadfence();
        int v = atomicAdd(&g_bar[idx], 1) + 1;
        if (v < GRID)
            while (*(volatile int*)&g_bar[idx] < GRID) __nanosleep(64);
    }
    __syncthreads();
    __threadfence();
}

extern "C" __global__ void __launch_bounds__(TS) k_all(const float* __restrict__ feats,
                                                       const void* __restrict__ labels,
                                                       const void* __restrict__ demog,
                                                       float* __restrict__ out) {
    extern __shared__ __align__(16) char sm[];
    float* ring = (float*)sm;                                   // 64 KB
    int*   sidx = (int*)(sm + NB * BR * ROWB);                  // 152 ints
    int*   sseg = sidx + CHUNK_PAD;                             // 152 ints
    int*   scr  = sseg + CHUNK_PAD;                             // 64 ints

    int bid = blockIdx.x, t = threadIdx.x;
    int lane = t & 31, w = t >> 5;
    int lo = bid * CHUNK;
    int hi = min(lo + CHUNK, NROWS);

    // ============ phase A: dtype detect + hist own rows + zero accumulators ============
    if (t < 32) {
        unsigned m = __ballot_sync(0xffffffffu, ((const int*)labels)[2 * t + 1] != 0);
        if (t == 0) scr[0] = (m == 0) ? 1 : 0;
    }
    __syncthreads();
    int is64 = scr[0];

    for (int i = t; i < CHUNK; i += TS) {
        int gi = lo + i;
        int sg = -1;
        if (gi < NROWS) {
            int lab = is64 ? (int)((const long long*)labels)[gi] : ((const int*)labels)[gi];
            int dem = is64 ? (int)((const long long*)demog)[gi]  : ((const int*)demog)[gi];
            sg = dem * NUM_LABELS + lab;
            atomicAdd(&g_cnt[sg], 1);
        }
        sseg[i] = sg;     // stash own segs for scatter
    }
    {
        float4 z = make_float4(0.f, 0.f, 0.f, 0.f);
        for (size_t j = (size_t)bid * TS + t; j < (size_t)NGROUP * 128; j += (size_t)GRID * TS)
            g_sums4[j] = z;
        if (bid == 0)
            for (int j = t; j < NGROUP; j += TS) g_ssq[j] = 0.f;
    }

    grid_bar(0);

    // ============ phase B: CTA 0 scans 2048 counts (16/thread) ============
    if (bid == 0) {
        int base = t * 16;
        int loc[16], s = 0;
        #pragma unroll
        for (int j = 0; j < 16; ++j) { int cc = g_cnt[base + j]; loc[j] = s; s += cc; }
        int v = s;
        #pragma unroll
        for (int d = 1; d < 32; d <<= 1) {
            int u = __shfl_up_sync(0xffffffffu, v, d);
            if (lane >= d) v += u;
        }
        if (lane == 31) scr[8 + w] = v;
        __syncthreads();
        if (t == 0) {
            int run = 0;
            #pragma unroll
            for (int j = 0; j < 4; ++j) { int x = scr[8 + j]; scr[8 + j] = run; run += x; }
        }
        __syncthreads();
        int excl = (v - s) + scr[8 + w];
        #pragma unroll
        for (int j = 0; j < 16; ++j) {
            g_off[base + j]    = excl + loc[j];
            g_cursor[base + j] = excl + loc[j];
        }
        if (t == TS - 1) g_off[NGROUP] = excl + s;
    }

    grid_bar(1);

    // ============ phase C: scatter own rows ============
    for (int i = t; i < CHUNK; i += TS) {
        int sg = sseg[i];
        if (sg >= 0) {
            int pos = atomicAdd(&g_cursor[sg], 1);
            g_sorted[pos] = lo + i;
            g_seg_sorted[pos] = sg;
        }
    }

    grid_bar(2);

    // ============ phase D: stream sorted chunk (R5 body + contained-group math) ============
    for (int i = t; i < CHUNK_PAD; i += TS) {
        int gi = lo + i;
        if (i < CHUNK && gi < NROWS) {
            sidx[i] = g_sorted[gi];
            sseg[i] = g_seg_sorted[gi];
        } else {
            sidx[i] = 0;
            sseg[i] = -1;
        }
    }
    __syncthreads();

    uint32_t ring_base = (uint32_t)__cvta_generic_to_shared(ring) + (uint32_t)t * 16u;
    const float* fbase = feats + (t << 2);

    #pragma unroll
    for (int p = 0; p < 3; ++p) {
        #pragma unroll
        for (int r = 0; r < BR; ++r) {
            const float* src = fbase + ((size_t)sidx[p * BR + r] << 9);
            cp_async16(ring_base + (uint32_t)((p & (NB - 1)) * BR + r) * ROWB, src);
        }
        cp_commit();
    }

    float4 acc = make_float4(0.f, 0.f, 0.f, 0.f);
    float  ssq = 0.f;
    int    cur = -1;
    double S0 = 0.0, S1 = 0.0, S2 = 0.0, S3 = 0.0;
    int    c0 = 0, c1 = 0, c2 = 0, c3 = 0;

    // flush cur: contained -> local double accumulation; boundary -> global atomics
    #define FLUSH_CUR()                                                          \
        do { if (cur >= 0) {                                                     \
            int s_ = g_off[cur], e_ = g_off[cur + 1];                            \
            if (s_ >= lo && e_ <= hi) {                                          \
                double dot_ = (double)acc.x * acc.x + (double)acc.y * acc.y +    \
                              (double)acc.z * acc.z + (double)acc.w * acc.w;     \
                double cn_ = (double)(e_ - s_);                                  \
                double con_ = ((double)ssq - dot_ / cn_) / cn_;                  \
                int d_ = cur >> 9;                                               \
                if (d_ == 0)      { S0 += con_; c0 += 1; }                       \
                else if (d_ == 1) { S1 += con_; c1 += 1; }                       \
                else if (d_ == 2) { S2 += con_; c2 += 1; }                       \
                else              { S3 += con_; c3 += 1; }                       \
            } else {                                                             \
                float* dst_ = (float*)g_sums4 + ((size_t)cur << 9) + (t << 2);   \
                atomicAdd(dst_ + 0, acc.x); atomicAdd(dst_ + 1, acc.y);          \
                atomicAdd(dst_ + 2, acc.z); atomicAdd(dst_ + 3, acc.w);          \
                float ws_ = ssq;                                                 \
                _Pragma("unroll")                                                \
                for (int o_ = 16; o_ > 0; o_ >>= 1)                              \
                    ws_ += __shfl_down_sync(0xffffffffu, ws_, o_);               \
                if (lane == 0) atomicAdd(&g_ssq[cur], ws_);                      \
            }                                                                    \
        } } while (0)

    for (int b = 0; b < NBATCH; ++b) {
        int k = NBATCH - 1 - b;
        if (k >= 2) cp_wait2(); else if (k == 1) cp_wait1(); else cp_wait0();

        const float* bp = ring + (size_t)((b & (NB - 1)) * BR) * DDIM + (t << 2);
        #pragma unroll
        for (int r = 0; r < BR; ++r) {
            int sg = sseg[b * BR + r];
            if (sg != cur) {
                FLUSH_CUR();
                acc = make_float4(0.f, 0.f, 0.f, 0.f);
                ssq = 0.f;
                cur = sg;
            }
            if (sg >= 0) {
                float4 v = *(const float4*)(bp + (size_t)r * DDIM);
                acc.x += v.x; acc.y += v.y; acc.z += v.z; acc.w += v.w;
                ssq += v.x * v.x + v.y * v.y + v.z * v.z + v.w * v.w;
            }
        }
        int nxt = b + 3;
        if (nxt < NBATCH) {
            #pragma unroll
            for (int r = 0; r < BR; ++r) {
                const float* src = fbase + ((size_t)sidx[nxt * BR + r] << 9);
                cp_async16(ring_base + (uint32_t)((nxt & (NB - 1)) * BR + r) * ROWB, src);
            }
            cp_commit();
        }
    }
    FLUSH_CUR();   // safety (pads usually already flushed the last group)

    // reduce contained contributions: warp shuffle -> 16 doubles in smem -> thread 0
    #pragma unroll
    for (int o = 16; o > 0; o >>= 1) {
        S0 += __shfl_down_sync(0xffffffffu, S0, o);
        S1 += __shfl_down_sync(0xffffffffu, S1, o);
        S2 += __shfl_down_sync(0xffffffffu, S2, o);
        S3 += __shfl_down_sync(0xffffffffu, S3, o);
    }
    __syncthreads();               // ring dead; reuse as double scratch
    double* dred = (double*)sm;
    if (lane == 0) {
        dred[w * 4 + 0] = S0; dred[w * 4 + 1] = S1;
        dred[w * 4 + 2] = S2; dred[w * 4 + 3] = S3;
    }
    __syncthreads();
    if (t == 0) {
        double a0 = dred[0] + dred[4] + dred[8]  + dred[12];
        double a1 = dred[1] + dred[5] + dred[9]  + dred[13];
        double a2 = dred[2] + dred[6] + dred[10] + dred[14];
        double a3 = dred[3] + dred[7] + dred[11] + dred[15];
        if (a0 != 0.0 || c0) atomicAdd(&g_intra[0], a0);
        if (a1 != 0.0 || c1) atomicAdd(&g_intra[1], a1);
        if (a2 != 0.0 || c2) atomicAdd(&g_intra[2], a2);
        if (a3 != 0.0 || c3) atomicAdd(&g_intra[3], a3);
        if (c0) atomicAdd(&g_present[0], c0);
        if (c1) atomicAdd(&g_present[1], c1);
        if (c2) atomicAdd(&g_present[2], c2);
        if (c3) atomicAdd(&g_present[3], c3);
    }

    grid_bar(3);

    // ============ phase E: boundary groups + cleanup ============
    for (int g = bid; g < NGROUP; g += GRID) {
        int s = g_off[g], e = g_off[g + 1];
        if (e > s) {
            int ca = s / CHUNK, cb = (e - 1) / CHUNK;
            if (ca != cb) {    // boundary group: finish from global accumulators
                float4 v = g_sums4[(size_t)g * 128 + t];
                double nn = (double)v.x * v.x + (double)v.y * v.y +
                            (double)v.z * v.z + (double)v.w * v.w;
                #pragma unroll
                for (int o = 16; o > 0; o >>= 1)
                    nn += __shfl_down_sync(0xffffffffu, nn, o);
                if (lane == 0) dred[16 + w] = nn;
                __syncthreads();
                if (t == 0) {
                    double normsq = dred[16] + dred[17] + dred[18] + dred[19];
                    double cnt = (double)(e - s);
                    double gm = ((double)g_ssq[g] - normsq / cnt) / cnt;
                    atomicAdd(&g_intra[g >> 9], gm);
                    atomicAdd(&g_present[g >> 9], 1);
                }
                __syncthreads();
            }
        }
        if (t == 0) g_cnt[g] = 0;    // clean for next replay
    }

    // ============ finalize: last CTA ============
    __shared__ int s_last;
    __threadfence();
    __syncthreads();
    if (t == 0)
        s_last = (atomicAdd(&g_fin, 1) == GRID - 1) ? 1 : 0;
    __syncthreads();
    if (!s_last) return;
    __threadfence();

    if (t == 0) {
        double intra[NUM_DEMOG];
        double mu = 0.0;
        #pragma unroll
        for (int d = 0; d < NUM_DEMOG; ++d) {
            int np = g_present[d] > 0 ? g_present[d] : 1;
            intra[d] = g_intra[d] / (double)np;
            mu += intra[d];
        }
        mu /= (double)NUM_DEMOG;
        double loss = 0.0;
        #pragma unroll
        for (int d = 0; d < NUM_DEMOG; ++d) loss += fabs(intra[d] - mu);
        loss /= (double)NUM_DEMOG;
        out[0] = (float)loss;

        // reset all cross-replay state
        #pragma unroll
        for (int d = 0; d < NUM_DEMOG; ++d) { g_intra[d] = 0.0; g_present[d] = 0; }
        g_bar[0] = 0; g_bar[1] = 0; g_bar[2] = 0; g_bar[3] = 0;
        g_fin = 0;
        __threadfence();
    }
}

extern "C" void kernel_launch(void* const* d_in, const int* in_sizes, int n_in,
                              void* d_out, int out_size) {
    const float* feats  = (const float*)d_in[0];
    const void*  labels = d_in[1];
    const void*  demog  = d_in[2];
    float* out = (float*)d_out;

    const int smem_total = NB * BR * ROWB + 2 * CHUNK_PAD * (int)sizeof(int)
                         + 64 * (int)sizeof(int) + 128;
    cudaFuncSetAttribute(k_all, cudaFuncAttributeMaxDynamicSharedMemorySize, smem_total);

    k_all<<<GRID, TS, smem_total>>>(feats, labels, demog, out);
}

// round 12
// speedup vs baseline: 1.1185x; 1.0005x over previous
#include <cuda_runtime.h>
#include <cstdint>

#define NROWS 65536
#define DDIM 512
#define NUM_LABELS 512
#define NUM_DEMOG 4
#define NGROUP (NUM_LABELS * NUM_DEMOG)

#define GRID_STREAM 444          /* 148 SMs x 3 CTAs: one wave */
#define TS 128                   /* stream block size (R5-measured best) */
#define CHUNK 148
#define BR 8
#define NB 4
#define CHUNK_PAD 152
#define NBATCH 19
#define ROWB 2048

#define PASS2_GRID 444

// ---- persistent device state ----
__device__ int    g_cnt[NGROUP];          // cleaned by k_pass2 (prev replay); BSS-zero first run
__device__ int    g_off[NGROUP + 1];
__device__ int    g_cursor[NGROUP];
__device__ int    g_seg[NROWS];
__device__ int    g_sorted[NROWS];
__device__ int    g_seg_sorted[NROWS];
__device__ float4 g_sums4[NGROUP * (DDIM / 4)];  // zeroed in k1 (L2-warm-modified)
__device__ float  g_ssq[NGROUP];                 // zeroed in k1
__device__ double g_gm[NGROUP];
__device__ int    g_fin;                         // reset by finalize

// ===== K1: zero accumulators + dtype detect + histogram (no internal sync) =====
__global__ void __launch_bounds__(1024) k1_zero_hist(const void* labels, const void* demog) {
    int gtid = blockIdx.x * 1024 + threadIdx.x;    // 148 x 1024 = 151552

    // dtype detect: warp 0 of each CTA via ballot over first 64 int32 words
    __shared__ int s_is64;
    if (threadIdx.x < 32) {
        unsigned m = __ballot_sync(0xffffffffu, ((const int*)labels)[2 * threadIdx.x + 1] != 0);
        if (threadIdx.x == 0) s_is64 = (m == 0) ? 1 : 0;
    }

    // zero 4MB sums (grid-stride, coalesced) + ssq
    float4 z = make_float4(0.f, 0.f, 0.f, 0.f);
    for (size_t j = gtid; j < (size_t)NGROUP * 128; j += 151552)
        g_sums4[j] = z;
    if (gtid < NGROUP) g_ssq[gtid] = 0.f;

    __syncthreads();
    int is64 = s_is64;

    // histogram (g_cnt was zeroed by previous replay's pass2 / BSS)
    if (gtid < NROWS) {
        int lab = is64 ? (int)((const long long*)labels)[gtid] : ((const int*)labels)[gtid];
        int dem = is64 ? (int)((const long long*)demog)[gtid]  : ((const int*)demog)[gtid];
        int seg = dem * NUM_LABELS + lab;
        g_seg[gtid] = seg;
        atomicAdd(&g_cnt[seg], 1);
    }
}

// ===== K2: single-CTA shuffle scan over 2048 counts =====
__global__ void __launch_bounds__(1024) k2_scan() {
    int t = threadIdx.x;
    int lane = t & 31, warp = t >> 5;
    int a = g_cnt[2 * t];
    int b = g_cnt[2 * t + 1];
    int pair = a + b;
    int v = pair;
    #pragma unroll
    for (int d = 1; d < 32; d <<= 1) {
        int u = __shfl_up_sync(0xffffffffu, v, d);
        if (lane >= d) v += u;
    }
    __shared__ int wsum[32];
    if (lane == 31) wsum[warp] = v;
    __syncthreads();
    if (warp == 0) {
        int w = wsum[lane];
        int x = w;
        #pragma unroll
        for (int d = 1; d < 32; d <<= 1) {
            int u = __shfl_up_sync(0xffffffffu, x, d);
            if (lane >= d) x += u;
        }
        wsum[lane] = x - w;
    }
    __syncthreads();
    int incl = v + wsum[warp];
    int excl = incl - pair;
    g_off[2 * t]        = excl;
    g_off[2 * t + 1]    = excl + a;
    g_cursor[2 * t]     = excl;
    g_cursor[2 * t + 1] = excl + a;
    if (t == 1023) g_off[NGROUP] = incl;
}

// ===== K3: scatter =====
__global__ void __launch_bounds__(1024) k3_scatter() {
    int i = blockIdx.x * 1024 + threadIdx.x;       // 64 x 1024
    int seg = g_seg[i];
    int pos = atomicAdd(&g_cursor[seg], 1);
    g_sorted[pos] = i;
    g_seg_sorted[pos] = seg;
}

// ---------------- cp.async helpers ----------------
__device__ __forceinline__ void cp_async16(uint32_t dst, const float* src) {
    asm volatile("cp.async.cg.shared.global [%0], [%1], 16;" :: "r"(dst), "l"(src));
}
__device__ __forceinline__ void cp_commit() { asm volatile("cp.async.commit_group;" ::: "memory"); }
__device__ __forceinline__ void cp_wait0() { asm volatile("cp.async.wait_group 0;" ::: "memory"); }
__device__ __forceinline__ void cp_wait1() { asm volatile("cp.async.wait_group 1;" ::: "memory"); }
__device__ __forceinline__ void cp_wait2() { asm volatile("cp.async.wait_group 2;" ::: "memory"); }

// ===== K4: stream — byte-exact R5 body (measured 27.6us @ 5.2 TB/s) =====
extern "C" __global__ void __launch_bounds__(TS) k_stream(const float* __restrict__ feats) {
    extern __shared__ __align__(16) char sm[];
    float* ring = (float*)sm;
    int*   sidx = (int*)(sm + NB * BR * ROWB);
    int*   sseg = sidx + CHUNK_PAD;

    int bid = blockIdx.x, t = threadIdx.x;
    int lo = bid * CHUNK;

    for (int i = t; i < CHUNK_PAD; i += TS) {
        int gi = lo + i;
        if (i < CHUNK && gi < NROWS) {
            sidx[i] = g_sorted[gi];
            sseg[i] = g_seg_sorted[gi];
        } else {
            sidx[i] = 0;
            sseg[i] = -1;
        }
    }
    __syncthreads();

    uint32_t ring_base = (uint32_t)__cvta_generic_to_shared(ring) + (uint32_t)t * 16u;
    const float* fbase = feats + (t << 2);

    #pragma unroll
    for (int p = 0; p < 3; ++p) {
        #pragma unroll
        for (int r = 0; r < BR; ++r) {
            const float* src = fbase + ((size_t)sidx[p * BR + r] << 9);
            cp_async16(ring_base + (uint32_t)((p & (NB - 1)) * BR + r) * ROWB, src);
        }
        cp_commit();
    }

    float4 acc = make_float4(0.f, 0.f, 0.f, 0.f);
    float  ssq = 0.f;
    int    cur = -1;
    int    lane = t & 31;

    for (int b = 0; b < NBATCH; ++b) {
        int k = NBATCH - 1 - b;
        if (k >= 2) cp_wait2(); else if (k == 1) cp_wait1(); else cp_wait0();

        const float* bp = ring + (size_t)((b & (NB - 1)) * BR) * DDIM + (t << 2);
        #pragma unroll
        for (int r = 0; r < BR; ++r) {
            int sg = sseg[b * BR + r];
            if (sg != cur) {
                if (cur >= 0) {
                    float* dst = (float*)g_sums4 + ((size_t)cur << 9) + (t << 2);
                    atomicAdd(dst + 0, acc.x);
                    atomicAdd(dst + 1, acc.y);
                    atomicAdd(dst + 2, acc.z);
                    atomicAdd(dst + 3, acc.w);
                    float ws = ssq;
                    #pragma unroll
                    for (int o = 16; o > 0; o >>= 1)
                        ws += __shfl_down_sync(0xffffffffu, ws, o);
                    if (lane == 0) atomicAdd(&g_ssq[cur], ws);
                }
                acc = make_float4(0.f, 0.f, 0.f, 0.f);
                ssq = 0.f;
                cur = sg;
            }
            if (sg >= 0) {
                float4 v = *(const float4*)(bp + (size_t)r * DDIM);
                acc.x += v.x; acc.y += v.y; acc.z += v.z; acc.w += v.w;
                ssq += v.x * v.x + v.y * v.y + v.z * v.z + v.w * v.w;
            }
        }
        int nxt = b + 3;
        if (nxt < NBATCH) {
            #pragma unroll
            for (int r = 0; r < BR; ++r) {
                const float* src = fbase + ((size_t)sidx[nxt * BR + r] << 9);
                cp_async16(ring_base + (uint32_t)((nxt & (NB - 1)) * BR + r) * ROWB, src);
            }
            cp_commit();
        }
    }
    if (cur >= 0) {
        float* dst = (float*)g_sums4 + ((size_t)cur << 9) + (t << 2);
        atomicAdd(dst + 0, acc.x);
        atomicAdd(dst + 1, acc.y);
        atomicAdd(dst + 2, acc.z);
        atomicAdd(dst + 3, acc.w);
        float ws = ssq;
        #pragma unroll
        for (int o = 16; o > 0; o >>= 1)
            ws += __shfl_down_sync(0xffffffffu, ws, o);
        if (lane == 0) atomicAdd(&g_ssq[cur], ws);
    }
}

// ===== K5: pass2 (444 CTAs, warp-per-group) + ticket finalize + self-clean =====
__global__ void __launch_bounds__(128) k5_pass2(float* __restrict__ out) {
    int bid = blockIdx.x, t = threadIdx.x;
    int lane = t & 31, w = t >> 5;    // 4 warps

    for (int g = w * PASS2_GRID + bid; g < NGROUP; g += 4 * PASS2_GRID) {
        double nn = 0.0;
        #pragma unroll
        for (int j = 0; j < 4; ++j) {
            float4 v = g_sums4[(size_t)g * 128 + lane + 32 * j];
            nn += (double)v.x * v.x + (double)v.y * v.y +
                  (double)v.z * v.z + (double)v.w * v.w;
        }
        #pragma unroll
        for (int o = 16; o > 0; o >>= 1)
            nn += __shfl_down_sync(0xffffffffu, nn, o);
        if (lane == 0) {
            int cnt = g_cnt[g];
            double den = (cnt > 0) ? (double)cnt : 1.0;
            g_gm[g] = ((double)g_ssq[g] - nn / den) / den;
            g_cnt[g] = 0;    // clean for next replay's K1 hist
        }
    }

    // ---- ticket finalize ----
    __shared__ int s_last;
    __threadfence();
    __syncthreads();
    if (t == 0)
        s_last = (atomicAdd(&g_fin, 1) == PASS2_GRID - 1) ? 1 : 0;
    __syncthreads();
    if (!s_last) return;
    __threadfence();

    __shared__ double fsum[NUM_DEMOG][128];
    __shared__ int    fcnt[NUM_DEMOG][128];
    double lsum[NUM_DEMOG] = {0.0, 0.0, 0.0, 0.0};
    int    lcnt[NUM_DEMOG] = {0, 0, 0, 0};
    for (int gg = t; gg < NGROUP; gg += 128) {
        if (g_off[gg + 1] - g_off[gg] > 0) {
            int d = gg >> 9;
            lsum[d] += g_gm[gg];
            lcnt[d] += 1;
        }
    }
    #pragma unroll
    for (int d = 0; d < NUM_DEMOG; ++d) { fsum[d][t] = lsum[d]; fcnt[d][t] = lcnt[d]; }
    __syncthreads();
    #pragma unroll
    for (int s = 64; s > 0; s >>= 1) {
        if (t < s) {
            #pragma unroll
            for (int d = 0; d < NUM_DEMOG; ++d) {
                fsum[d][t] += fsum[d][t + s];
                fcnt[d][t] += fcnt[d][t + s];
            }
        }
        __syncthreads();
    }
    if (t == 0) {
        double intra[NUM_DEMOG];
        double mu = 0.0;
        #pragma unroll
        for (int d = 0; d < NUM_DEMOG; ++d) {
            int np = fcnt[d][0] > 0 ? fcnt[d][0] : 1;
            intra[d] = fsum[d][0] / (double)np;
            mu += intra[d];
        }
        mu /= (double)NUM_DEMOG;
        double loss = 0.0;
        #pragma unroll
        for (int d = 0; d < NUM_DEMOG; ++d) loss += fabs(intra[d] - mu);
        loss /= (double)NUM_DEMOG;
        out[0] = (float)loss;
        g_fin = 0;     // reset ticket for next replay
        __threadfence();
    }
}

extern "C" void kernel_launch(void* const* d_in, const int* in_sizes, int n_in,
                              void* d_out, int out_size) {
    const float* feats  = (const float*)d_in[0];
    const void*  labels = d_in[1];
    const void*  demog  = d_in[2];
    float* out = (float*)d_out;

    const int smem_stream = NB * BR * ROWB + 2 * CHUNK_PAD * (int)sizeof(int) + 128;
    cudaFuncSetAttribute(k_stream, cudaFuncAttributeMaxDynamicSharedMemorySize, smem_stream);

    k1_zero_hist<<<148, 1024>>>(labels, demog);
    k2_scan<<<1, 1024>>>();
    k3_scatter<<<64, 1024>>>();
    k_stream<<<GRID_STREAM, TS, smem_stream>>>(feats);
    k5_pass2<<<PASS2_GRID, 128>>>(out);
}

// round 13
// speedup vs baseline: 1.2589x; 1.1256x over previous
#include <cuda_runtime.h>
#include <cstdint>

#define NROWS 65536
#define DDIM 512
#define NUM_LABELS 512
#define NUM_DEMOG 4
#define NGROUP (NUM_LABELS * NUM_DEMOG)

#define GRID_STREAM 444
#define TS 128
#define CHUNK 148
#define BR 8
#define NB 4
#define CHUNK_PAD 152
#define NBATCH 19
#define ROWB 2048

// ---- persistent device state (BSS zero; self-cleaning) ----
__device__ int    g_cnt[NGROUP];          // zeroed by k5 finalize (prev replay)
__device__ int    g_off[NGROUP + 1];
__device__ int    g_cursor[NGROUP];
__device__ int    g_seg[NROWS];
__device__ int    g_sorted[NROWS];
__device__ int    g_seg_sorted[NROWS];
__device__ float4 g_sums4[NGROUP * (DDIM / 4)];  // ONLY boundary groups dirtied; k5 re-zeroes them
__device__ float  g_ssq[NGROUP];                 // same
__device__ double g_intra[NUM_DEMOG];            // reset by finalize
__device__ int    g_present[NUM_DEMOG];          // reset by finalize
__device__ int    g_fin;                         // reset by finalize

// ===== K1: dtype detect + histogram + seg stash (traffic ~1.3 MB) =====
__global__ void __launch_bounds__(1024) k1_hist(const void* labels, const void* demog) {
    int i = blockIdx.x * 1024 + threadIdx.x;    // 64 x 1024 = 65536
    __shared__ int s_is64;
    if (threadIdx.x < 32) {
        unsigned m = __ballot_sync(0xffffffffu, ((const int*)labels)[2 * threadIdx.x + 1] != 0);
        if (threadIdx.x == 0) s_is64 = (m == 0) ? 1 : 0;
    }
    __syncthreads();
    int is64 = s_is64;
    int lab = is64 ? (int)((const long long*)labels)[i] : ((const int*)labels)[i];
    int dem = is64 ? (int)((const long long*)demog)[i]  : ((const int*)demog)[i];
    int seg = dem * NUM_LABELS + lab;
    g_seg[i] = seg;
    atomicAdd(&g_cnt[seg], 1);
}

// ===== K2: single-CTA shuffle scan over 2048 counts =====
__global__ void __launch_bounds__(1024) k2_scan() {
    int t = threadIdx.x;
    int lane = t & 31, warp = t >> 5;
    int a = g_cnt[2 * t];
    int b = g_cnt[2 * t + 1];
    int pair = a + b;
    int v = pair;
    #pragma unroll
    for (int d = 1; d < 32; d <<= 1) {
        int u = __shfl_up_sync(0xffffffffu, v, d);
        if (lane >= d) v += u;
    }
    __shared__ int wsum[32];
    if (lane == 31) wsum[warp] = v;
    __syncthreads();
    if (warp == 0) {
        int w = wsum[lane];
        int x = w;
        #pragma unroll
        for (int d = 1; d < 32; d <<= 1) {
            int u = __shfl_up_sync(0xffffffffu, x, d);
            if (lane >= d) x += u;
        }
        wsum[lane] = x - w;
    }
    __syncthreads();
    int incl = v + wsum[warp];
    int excl = incl - pair;
    g_off[2 * t]        = excl;
    g_off[2 * t + 1]    = excl + a;
    g_cursor[2 * t]     = excl;
    g_cursor[2 * t + 1] = excl + a;
    if (t == 1023) g_off[NGROUP] = incl;
}

// ===== K3: scatter =====
__global__ void __launch_bounds__(1024) k3_scatter() {
    int i = blockIdx.x * 1024 + threadIdx.x;
    int seg = g_seg[i];
    int pos = atomicAdd(&g_cursor[seg], 1);
    g_sorted[pos] = i;
    g_seg_sorted[pos] = seg;
}

// ---------------- cp.async helpers ----------------
__device__ __forceinline__ void cp_async16(uint32_t dst, const float* src) {
    asm volatile("cp.async.cg.shared.global [%0], [%1], 16;" :: "r"(dst), "l"(src));
}
__device__ __forceinline__ void cp_commit() { asm volatile("cp.async.commit_group;" ::: "memory"); }
__device__ __forceinline__ void cp_wait0() { asm volatile("cp.async.wait_group 0;" ::: "memory"); }
__device__ __forceinline__ void cp_wait1() { asm volatile("cp.async.wait_group 1;" ::: "memory"); }
__device__ __forceinline__ void cp_wait2() { asm volatile("cp.async.wait_group 2;" ::: "memory"); }

// ===== K4: stream (R12 body) + contained-group local math (R11-validated) =====
extern "C" __global__ void __launch_bounds__(TS) k_stream(const float* __restrict__ feats) {
    extern __shared__ __align__(16) char sm[];
    float* ring = (float*)sm;
    int*   sidx = (int*)(sm + NB * BR * ROWB);
    int*   sseg = sidx + CHUNK_PAD;

    int bid = blockIdx.x, t = threadIdx.x;
    int lane = t & 31, w = t >> 5;
    int lo = bid * CHUNK;
    int hi = min(lo + CHUNK, NROWS);

    for (int i = t; i < CHUNK_PAD; i += TS) {
        int gi = lo + i;
        if (i < CHUNK && gi < NROWS) {
            sidx[i] = g_sorted[gi];
            sseg[i] = g_seg_sorted[gi];
        } else {
            sidx[i] = 0;
            sseg[i] = -1;
        }
    }
    __syncthreads();

    uint32_t ring_base = (uint32_t)__cvta_generic_to_shared(ring) + (uint32_t)t * 16u;
    const float* fbase = feats + (t << 2);

    #pragma unroll
    for (int p = 0; p < 3; ++p) {
        #pragma unroll
        for (int r = 0; r < BR; ++r) {
            const float* src = fbase + ((size_t)sidx[p * BR + r] << 9);
            cp_async16(ring_base + (uint32_t)((p & (NB - 1)) * BR + r) * ROWB, src);
        }
        cp_commit();
    }

    float4 acc = make_float4(0.f, 0.f, 0.f, 0.f);
    float  ssq = 0.f;
    int    cur = -1;
    double S0 = 0.0, S1 = 0.0, S2 = 0.0, S3 = 0.0;
    int    c0 = 0, c1 = 0, c2 = 0, c3 = 0;   // warp-uniform counts (t0's value used)

    #define FLUSH_CUR()                                                          \
        do { if (cur >= 0) {                                                     \
            int s_ = g_off[cur], e_ = g_off[cur + 1];                            \
            if (s_ >= lo && e_ <= hi) {                                          \
                double dot_ = (double)acc.x * acc.x + (double)acc.y * acc.y +    \
                              (double)acc.z * acc.z + (double)acc.w * acc.w;     \
                double cn_ = (double)(e_ - s_);                                  \
                double con_ = ((double)ssq - dot_ / cn_) / cn_;                  \
                int d_ = cur >> 9;                                               \
                if (d_ == 0)      { S0 += con_; c0 += 1; }                       \
                else if (d_ == 1) { S1 += con_; c1 += 1; }                       \
                else if (d_ == 2) { S2 += con_; c2 += 1; }                       \
                else              { S3 += con_; c3 += 1; }                       \
            } else {                                                             \
                float* dst_ = (float*)g_sums4 + ((size_t)cur << 9) + (t << 2);   \
                atomicAdd(dst_ + 0, acc.x); atomicAdd(dst_ + 1, acc.y);          \
                atomicAdd(dst_ + 2, acc.z); atomicAdd(dst_ + 3, acc.w);          \
                float ws_ = ssq;                                                 \
                _Pragma("unroll")                                                \
                for (int o_ = 16; o_ > 0; o_ >>= 1)                              \
                    ws_ += __shfl_down_sync(0xffffffffu, ws_, o_);               \
                if (lane == 0) atomicAdd(&g_ssq[cur], ws_);                      \
            }                                                                    \
        } } while (0)

    for (int b = 0; b < NBATCH; ++b) {
        int k = NBATCH - 1 - b;
        if (k >= 2) cp_wait2(); else if (k == 1) cp_wait1(); else cp_wait0();

        const float* bp = ring + (size_t)((b & (NB - 1)) * BR) * DDIM + (t << 2);
        #pragma unroll
        for (int r = 0; r < BR; ++r) {
            int sg = sseg[b * BR + r];
            if (sg != cur) {
                FLUSH_CUR();
                acc = make_float4(0.f, 0.f, 0.f, 0.f);
                ssq = 0.f;
                cur = sg;
            }
            if (sg >= 0) {
                float4 v = *(const float4*)(bp + (size_t)r * DDIM);
                acc.x += v.x; acc.y += v.y; acc.z += v.z; acc.w += v.w;
                ssq += v.x * v.x + v.y * v.y + v.z * v.z + v.w * v.w;
            }
        }
        int nxt = b + 3;
        if (nxt < NBATCH) {
            #pragma unroll
            for (int r = 0; r < BR; ++r) {
                const float* src = fbase + ((size_t)sidx[nxt * BR + r] << 9);
                cp_async16(ring_base + (uint32_t)((nxt & (NB - 1)) * BR + r) * ROWB, src);
            }
            cp_commit();
        }
    }
    FLUSH_CUR();

    // CTA-local reduce of contained contributions -> 8 global atomics
    #pragma unroll
    for (int o = 16; o > 0; o >>= 1) {
        S0 += __shfl_down_sync(0xffffffffu, S0, o);
        S1 += __shfl_down_sync(0xffffffffu, S1, o);
        S2 += __shfl_down_sync(0xffffffffu, S2, o);
        S3 += __shfl_down_sync(0xffffffffu, S3, o);
    }
    __syncthreads();                // ring dead; alias double scratch
    double* dred = (double*)sm;
    if (lane == 0) {
        dred[w * 4 + 0] = S0; dred[w * 4 + 1] = S1;
        dred[w * 4 + 2] = S2; dred[w * 4 + 3] = S3;
    }
    __syncthreads();
    if (t == 0) {
        double a0 = dred[0] + dred[4] + dred[8]  + dred[12];
        double a1 = dred[1] + dred[5] + dred[9]  + dred[13];
        double a2 = dred[2] + dred[6] + dred[10] + dred[14];
        double a3 = dred[3] + dred[7] + dred[11] + dred[15];
        if (c0) { atomicAdd(&g_intra[0], a0); atomicAdd(&g_present[0], c0); }
        if (c1) { atomicAdd(&g_intra[1], a1); atomicAdd(&g_present[1], c1); }
        if (c2) { atomicAdd(&g_intra[2], a2); atomicAdd(&g_present[2], c2); }
        if (c3) { atomicAdd(&g_intra[3], a3); atomicAdd(&g_present[3], c3); }
    }
}

// ===== K5: boundary groups only + ticket finalize + state reset =====
__global__ void __launch_bounds__(128) k5_fin(float* __restrict__ out) {
    __shared__ double wred[4];
    int bid = blockIdx.x, t = threadIdx.x;   // 444 x 128
    int lane = t & 31, w = t >> 5;

    for (int g = bid; g < NGROUP; g += GRID_STREAM) {
        int s = g_off[g], e = g_off[g + 1];
        if (e <= s) continue;
        int ca = s / CHUNK, cb = (e - 1) / CHUNK;
        if (ca == cb) continue;              // contained: handled in k_stream
        // boundary group: finish from global accumulators, then zero them
        float4 v = g_sums4[(size_t)g * 128 + t];
        g_sums4[(size_t)g * 128 + t] = make_float4(0.f, 0.f, 0.f, 0.f);
        double nn = (double)v.x * v.x + (double)v.y * v.y +
                    (double)v.z * v.z + (double)v.w * v.w;
        #pragma unroll
        for (int o = 16; o > 0; o >>= 1)
            nn += __shfl_down_sync(0xffffffffu, nn, o);
        if (lane == 0) wred[w] = nn;
        __syncthreads();
        if (t == 0) {
            double normsq = wred[0] + wred[1] + wred[2] + wred[3];
            double cnt = (double)(e - s);
            double gm = ((double)g_ssq[g] - normsq / cnt) / cnt;
            g_ssq[g] = 0.f;
            atomicAdd(&g_intra[g >> 9], gm);
            atomicAdd(&g_present[g >> 9], 1);
        }
        __syncthreads();
    }

    // ---- ticket finalize ----
    __shared__ int s_last;
    __threadfence();
    __syncthreads();
    if (t == 0)
        s_last = (atomicAdd(&g_fin, 1) == GRID_STREAM - 1) ? 1 : 0;
    __syncthreads();
    if (!s_last) return;
    __threadfence();

    // reset g_cnt for next replay's hist (2048 ints, one CTA)
    for (int g = t; g < NGROUP; g += 128) g_cnt[g] = 0;

    if (t == 0) {
        double intra[NUM_DEMOG];
        double mu = 0.0;
        #pragma unroll
        for (int d = 0; d < NUM_DEMOG; ++d) {
            int np = g_present[d] > 0 ? g_present[d] : 1;
            intra[d] = g_intra[d] / (double)np;
            mu += intra[d];
        }
        mu /= (double)NUM_DEMOG;
        double loss = 0.0;
        #pragma unroll
        for (int d = 0; d < NUM_DEMOG; ++d) loss += fabs(intra[d] - mu);
        loss /= (double)NUM_DEMOG;
        out[0] = (float)loss;

        #pragma unroll
        for (int d = 0; d < NUM_DEMOG; ++d) { g_intra[d] = 0.0; g_present[d] = 0; }
        g_fin = 0;
        __threadfence();
    }
}

extern "C" void kernel_launch(void* const* d_in, const int* in_sizes, int n_in,
                              void* d_out, int out_size) {
    const float* feats  = (const float*)d_in[0];
    const void*  labels = d_in[1];
    const void*  demog  = d_in[2];
    float* out = (float*)d_out;

    const int smem_stream = NB * BR * ROWB + 2 * CHUNK_PAD * (int)sizeof(int) + 128;
    cudaFuncSetAttribute(k_stream, cudaFuncAttributeMaxDynamicSharedMemorySize, smem_stream);

    k1_hist<<<64, 1024>>>(labels, demog);
    k2_scan<<<1, 1024>>>();
    k3_scatter<<<64, 1024>>>();
    k_stream<<<GRID_STREAM, TS, smem_stream>>>(feats);
    k5_fin<<<GRID_STREAM, 128>>>(out);
}